// round 8
// baseline (speedup 1.0000x reference)
#include <cuda_runtime.h>
#include <cuda_fp16.h>
#include <math.h>
#include <stdint.h>

// Problem constants
#define T_STEPS 1000
#define BATCH   128
#define N_IN    3
#define N_H     256
#define N_PC    256
#define N_HD    12
#define N_IC    268

// Output layout (float32, concatenated in reference tuple order)
#define OFF_HD   0L
#define OFF_PC   (OFF_HD  + (long)T_STEPS * BATCH * N_HD)
#define OFF_BOT  (OFF_PC  + (long)T_STEPS * BATCH * N_PC)
#define OFF_RNN  (OFF_BOT + (long)T_STEPS * BATCH * N_H)
#define OFF_CELL (OFF_RNN + (long)T_STEPS * BATCH * N_H)

// Tile swizzle: rows of 512B; XOR byte-offset bits[4:6] with (row&7).
#define TSWZ(kb, r) ((kb) ^ (((r) & 7) << 4))

#define NREC   128
#define NGEMM  168
#define GQ     (NGEMM / 4)   // 42 blocks per N-quarter

// ---------------------------------------------------------------------------
// Device-global scratch (allocation-free)
// ---------------------------------------------------------------------------
__device__ float g_h0[BATCH * N_H];
__device__ float g_c0[BATCH * N_H];
// Y fp16, pre-swizzled tile images: tile t = [128 batch rows][256 h], 64KB each.
__device__ __half g_yimg[(long)T_STEPS * 128 * 256];
// pc W fp16 images per N-quarter: 64 rows x 256 k = 32KB each.
__device__ __half g_wimg[4][16384];
// hd W fp16 image: 16 rows (12 used) x 256 k = 8KB.
__device__ __half g_hdimg[4096];
// producer->consumer flags: group g done when g_flags[g] == NREC
__device__ int g_flags[64];

// ---------------------------------------------------------------------------
// PTX helpers (base-arch only)
// ---------------------------------------------------------------------------
__device__ __forceinline__ uint32_t smem_u32(const void* p) {
    uint32_t a;
    asm("{ .reg .u64 t; cvta.to.shared.u64 t, %1; cvt.u32.u64 %0, t; }" : "=r"(a) : "l"(p));
    return a;
}
__device__ __forceinline__ void cp_async16(uint32_t dst, const void* src) {
    asm volatile("cp.async.cg.shared.global [%0], [%1], 16;" :: "r"(dst), "l"(src) : "memory");
}
__device__ __forceinline__ void cp_commit() {
    asm volatile("cp.async.commit_group;" ::: "memory");
}
__device__ __forceinline__ void cp_wait1() {
    asm volatile("cp.async.wait_group 1;" ::: "memory");
}
__device__ __forceinline__ void cp_wait0() {
    asm volatile("cp.async.wait_group 0;" ::: "memory");
}
__device__ __forceinline__ void ldsm4(uint32_t& r0, uint32_t& r1, uint32_t& r2, uint32_t& r3,
                                      uint32_t addr) {
    asm volatile("ldmatrix.sync.aligned.m8n8.x4.shared.b16 {%0,%1,%2,%3}, [%4];"
                 : "=r"(r0), "=r"(r1), "=r"(r2), "=r"(r3) : "r"(addr));
}
__device__ __forceinline__ void mma16816(float* c, const uint32_t* a, uint32_t b0, uint32_t b1) {
    asm volatile("mma.sync.aligned.m16n8k16.row.col.f32.f16.f16.f32 "
                 "{%0,%1,%2,%3}, {%4,%5,%6,%7}, {%8,%9}, {%0,%1,%2,%3};"
                 : "+f"(c[0]), "+f"(c[1]), "+f"(c[2]), "+f"(c[3])
                 : "r"(a[0]), "r"(a[1]), "r"(a[2]), "r"(a[3]), "r"(b0), "r"(b1));
}
__device__ __forceinline__ void stcs1(float* p, float v) {
    asm volatile("st.global.cs.f32 [%0], %1;" :: "l"(p), "f"(v) : "memory");
}
__device__ __forceinline__ void stcs2(float* p, float2 v) {
    asm volatile("st.global.cs.v2.f32 [%0], {%1,%2};" :: "l"(p), "f"(v.x), "f"(v.y) : "memory");
}
__device__ __forceinline__ void red_release_add(int* p) {
    asm volatile("red.release.gpu.global.add.s32 [%0], 1;" :: "l"(p) : "memory");
}
__device__ __forceinline__ int ld_acquire(const int* p) {
    int v;
    asm volatile("ld.acquire.gpu.global.s32 %0, [%1];" : "=r"(v) : "l"(p) : "memory");
    return v;
}

// ---------------------------------------------------------------------------
// Kernel 0: zero flags (every call — graph replay safe)
// ---------------------------------------------------------------------------
__global__ void zero_flags_kernel() {
    g_flags[threadIdx.x] = 0;
}

// ---------------------------------------------------------------------------
// Kernel 1: initial conditions
// ---------------------------------------------------------------------------
__global__ void init_kernel(const float* __restrict__ ic,
                            const float* __restrict__ sew, const float* __restrict__ seb,
                            const float* __restrict__ cew, const float* __restrict__ ceb) {
    __shared__ float icr[N_IC];
    int b = blockIdx.x;
    int h = threadIdx.x;
    for (int i = h; i < N_IC; i += N_H) icr[i] = ic[b * N_IC + i];
    __syncthreads();

    float accS = seb[h];
    float accC = ceb[h];
    #pragma unroll 4
    for (int k = 0; k < N_IC; k++) {
        float v = icr[k];
        accS = fmaf(v, sew[k * N_H + h], accS);
        accC = fmaf(v, cew[k * N_H + h], accC);
    }
    g_h0[b * N_H + h] = 1.0f / (1.0f + expf(-accS));
    g_c0[b * N_H + h] = 1.0f / (1.0f + expf(-accC));
}

// ---------------------------------------------------------------------------
// Kernel 2a: pc W -> fp16, pre-swizzled images per N-quarter.
// ---------------------------------------------------------------------------
__global__ void wconv_kernel(const float* __restrict__ W) {
    int k = blockIdx.x;    // 0..255
    int n = threadIdx.x;   // 0..255
    float w = W[k * 256 + n];
    int q = n >> 6, nl = n & 63;
    int byteoff = nl * 512 + TSWZ(k * 2, nl);
    g_wimg[q][byteoff >> 1] = __float2half_rn(w);
}

// Kernel 2b: hd W [256,12] -> padded 16-row fp16 image.
__global__ void wconv_hd_kernel(const float* __restrict__ W) {
    int n = blockIdx.x;    // 0..15
    int k = threadIdx.x;   // 0..255
    float w = (n < N_HD) ? W[k * N_HD + n] : 0.0f;
    int byteoff = n * 512 + TSWZ(k * 2, n);
    g_hdimg[byteoff >> 1] = __float2half_rn(w);
}

// ---------------------------------------------------------------------------
// Fused kernel: blocks 0..127 = recurrence (producer),
//               blocks 128..295 = persistent GEMM (consumer).
// ---------------------------------------------------------------------------
#define SM_A   0
#define SM_B   65536
#define SM_HD  98304
#define SM_TOT 106496

__global__ void __launch_bounds__(256, 2) fused_kernel(
        const float* __restrict__ x,
        const float* __restrict__ iw,
        const float* __restrict__ lvec,
        const float* __restrict__ bvec,
        const float* __restrict__ pcb,
        const float* __restrict__ hdb,
        float* __restrict__ out) {
    extern __shared__ char smem[];
    const int tid = threadIdx.x;

    if (blockIdx.x < NREC) {
        // ============ PRODUCER: recurrence ============
        float* xs = (float*)smem;  // 12 KB of the dynamic region
        const int b = blockIdx.x;
        const int h = tid;

        for (int i = tid; i < T_STEPS * N_IN; i += 256) {
            int t = i / N_IN, c = i - t * N_IN;
            xs[i] = x[((long)t * BATCH + b) * N_IN + c];
        }

        const float w0 = iw[0 * N_H + h];
        const float w1 = iw[1 * N_H + h];
        const float w2 = iw[2 * N_H + h];
        const float lv = lvec[h];
        const float bv = bvec[h];
        float y = g_h0[b * N_H + h];
        float s = g_c0[b * N_H + h];
        __syncthreads();

        float* yp1 = out + OFF_BOT + (long)b * N_H + h;
        float* yp2 = out + OFF_RNN + (long)b * N_H + h;
        float* sp  = out + OFF_CELL + (long)b * N_H + h;
        __half* yi = g_yimg + ((b * 512 + TSWZ(h * 2, b)) >> 1);

        const long strideT = (long)BATCH * N_H;  // 32768

        for (int t = 0; t < T_STEPS; t++) {
            const float x0 = xs[t * 3 + 0];
            const float x1 = xs[t * 3 + 1];
            const float x2 = xs[t * 3 + 2];
            float xw  = fmaf(x2, w2, fmaf(x1, w1, x0 * w0));
            float pre = xw + y + lv * s * (1.0f - y);
            s = fmaxf(pre, 0.0f);
            y = (s + bv > 0.0f) ? 1.0f : 0.0f;

            long o = (long)t * strideT;
            stcs1(yp1 + o, y);
            stcs1(yp2 + o, y);
            stcs1(sp + o, s);
            yi[(long)t * 32768] = __float2half_rn(y);   // plain store: keep L2-hot

            if (((t & 15) == 15) || (t == T_STEPS - 1)) {
                __syncthreads();                         // all lanes' stores done
                if (tid == 0) red_release_add(&g_flags[t >> 4]);
            }
        }
    } else {
        // ============ CONSUMER: persistent GEMM ============
        uint32_t sb = smem_u32(smem);
        const int wid = tid >> 5, lane = tid & 31;
        const int gid = (int)blockIdx.x - NREC;   // 0..167
        const int q   = gid & 3;                  // fixed N-quarter
        const int t0  = gid >> 2;                 // 0..41
        const int warp_m = wid & 3, warp_n = wid >> 2;  // 4m x 2n
        const bool hdq = (q == 0) && (warp_n == 0);

        // Load B quarter (32KB) once; hd image (8KB) for q==0 blocks.
        {
            const char* gW = (const char*)(g_wimg[q]);
            #pragma unroll
            for (int i = 0; i < 8; i++)
                cp_async16(sb + SM_B + (tid + i * 256) * 16, gW + (tid + i * 256) * 16);
            if (q == 0) {
                const char* gH = (const char*)g_hdimg;
                #pragma unroll
                for (int i = 0; i < 2; i++)
                    cp_async16(sb + SM_HD + (tid + i * 256) * 16, gH + (tid + i * 256) * 16);
            }
            cp_commit();
            cp_wait0();
        }
        __syncthreads();

        const int g  = lane >> 2;
        const int c2 = (lane & 3) * 2;
        const int colBase = q * 64 + warp_n * 32;

        float2 bias2[4];
        #pragma unroll
        for (int ni = 0; ni < 4; ni++) {
            bias2[ni].x = __ldg(pcb + colBase + ni * 8 + c2);
            bias2[ni].y = __ldg(pcb + colBase + ni * 8 + c2 + 1);
        }
        float hb0x = 0.f, hb0y = 0.f, hb1x = 0.f, hb1y = 0.f;
        if (hdq) {
            hb0x = __ldg(hdb + c2);
            hb0y = __ldg(hdb + c2 + 1);
            if (c2 < 4) { hb1x = __ldg(hdb + 8 + c2); hb1y = __ldg(hdb + 8 + c2 + 1); }
        }

        const int arow0 = warp_m * 32 + (lane & 15);
        const int brow0 = warp_n * 32 + (lane & 15);
        const int hrow0 = (lane & 15);
        const int ksub  = (lane >> 4) * 16;
        const int r_ld  = tid >> 1;        // 0..127
        const int p_ld  = (tid & 1) * 128; // byte offset within a 256B half-row

        for (int t = t0; t < T_STEPS; t += GQ) {
            // Wait for tile t (group t>>4 complete).
            if (tid == 0) {
                const int* fp = &g_flags[t >> 4];
                while (ld_acquire(fp) < NREC) __nanosleep(64);
            }
            __syncthreads();   // releases block; also guards A-buffer reuse

            // Load A tile in two k-halves (columns [0,128) then [128,256)).
            const char* gA = (const char*)(g_yimg + (long)t * 32768);
            #pragma unroll
            for (int j = 0; j < 8; j++)
                cp_async16(sb + SM_A + r_ld * 512 + p_ld + j * 16,
                           gA + r_ld * 512 + p_ld + j * 16);
            cp_commit();
            #pragma unroll
            for (int j = 0; j < 8; j++)
                cp_async16(sb + SM_A + r_ld * 512 + 256 + p_ld + j * 16,
                           gA + r_ld * 512 + 256 + p_ld + j * 16);
            cp_commit();

            float acc[2][4][4];
            #pragma unroll
            for (int i = 0; i < 2; i++)
                #pragma unroll
                for (int j = 0; j < 4; j++)
                    #pragma unroll
                    for (int p = 0; p < 4; p++) acc[i][j][p] = 0.0f;
            float acch[2][2][4];
            #pragma unroll
            for (int i = 0; i < 2; i++)
                #pragma unroll
                for (int j = 0; j < 2; j++)
                    #pragma unroll
                    for (int p = 0; p < 4; p++) acch[i][j][p] = 0.0f;

            #pragma unroll
            for (int kh = 0; kh < 2; kh++) {
                if (kh == 0) cp_wait1(); else cp_wait0();
                __syncthreads();
                #pragma unroll
                for (int kk = 0; kk < 8; kk++) {
                    const int kb = (kh * 8 + kk) * 32 + ksub;
                    uint32_t a[2][4], bfr[2][4];
                    #pragma unroll
                    for (int mi = 0; mi < 2; mi++) {
                        int r = arow0 + mi * 16;
                        ldsm4(a[mi][0], a[mi][1], a[mi][2], a[mi][3],
                              sb + SM_A + r * 512 + TSWZ(kb, r));
                    }
                    #pragma unroll
                    for (int ni = 0; ni < 2; ni++) {
                        int r = brow0 + ni * 16;
                        ldsm4(bfr[ni][0], bfr[ni][1], bfr[ni][2], bfr[ni][3],
                              sb + SM_B + r * 512 + TSWZ(kb, r));
                    }
                    #pragma unroll
                    for (int mi = 0; mi < 2; mi++)
                        #pragma unroll
                        for (int ni = 0; ni < 2; ni++) {
                            mma16816(acc[mi][ni * 2],     a[mi], bfr[ni][0], bfr[ni][2]);
                            mma16816(acc[mi][ni * 2 + 1], a[mi], bfr[ni][1], bfr[ni][3]);
                        }
                    if (hdq) {
                        uint32_t hb[4];
                        ldsm4(hb[0], hb[1], hb[2], hb[3],
                              sb + SM_HD + hrow0 * 512 + TSWZ(kb, hrow0));
                        #pragma unroll
                        for (int mi = 0; mi < 2; mi++) {
                            mma16816(acch[mi][0], a[mi], hb[0], hb[2]);
                            mma16816(acch[mi][1], a[mi], hb[1], hb[3]);
                        }
                    }
                }
            }

            // Epilogue: pc
            const long rowBase = (long)t * 128 + warp_m * 32;
            float* outpc = out + OFF_PC;
            #pragma unroll
            for (int mi = 0; mi < 2; mi++) {
                float* r0 = outpc + (rowBase + mi * 16 + g) * N_PC + colBase + c2;
                float* r1 = r0 + 8 * N_PC;
                #pragma unroll
                for (int ni = 0; ni < 4; ni++) {
                    stcs2(r0 + ni * 8, make_float2(acc[mi][ni][0] + bias2[ni].x,
                                                   acc[mi][ni][1] + bias2[ni].y));
                    stcs2(r1 + ni * 8, make_float2(acc[mi][ni][2] + bias2[ni].x,
                                                   acc[mi][ni][3] + bias2[ni].y));
                }
            }
            // Epilogue: hd (cols 0..11 of the padded 16)
            if (hdq) {
                float* outhd = out + OFF_HD;
                #pragma unroll
                for (int mi = 0; mi < 2; mi++) {
                    long r = rowBase + mi * 16 + g;
                    float* o0 = outhd + r * N_HD;
                    float* o1 = o0 + 8L * N_HD;
                    stcs2(o0 + c2, make_float2(acch[mi][0][0] + hb0x, acch[mi][0][1] + hb0y));
                    stcs2(o1 + c2, make_float2(acch[mi][0][2] + hb0x, acch[mi][0][3] + hb0y));
                    if (c2 < 4) {
                        stcs2(o0 + 8 + c2, make_float2(acch[mi][1][0] + hb1x, acch[mi][1][1] + hb1y));
                        stcs2(o1 + 8 + c2, make_float2(acch[mi][1][2] + hb1x, acch[mi][1][3] + hb1y));
                    }
                }
            }
        }
    }
}

// ---------------------------------------------------------------------------
extern "C" void kernel_launch(void* const* d_in, const int* in_sizes, int n_in,
                              void* d_out, int out_size) {
    const float* x    = (const float*)d_in[0];
    const float* ic   = (const float*)d_in[1];
    const float* iw   = (const float*)d_in[2];
    const float* l    = (const float*)d_in[3];
    const float* b    = (const float*)d_in[4];
    const float* sew  = (const float*)d_in[5];
    const float* seb  = (const float*)d_in[6];
    const float* cew  = (const float*)d_in[7];
    const float* ceb  = (const float*)d_in[8];
    const float* pcw  = (const float*)d_in[9];
    const float* pcb  = (const float*)d_in[10];
    const float* hdw  = (const float*)d_in[11];
    const float* hdb  = (const float*)d_in[12];
    float* out = (float*)d_out;

    cudaFuncSetAttribute(fused_kernel, cudaFuncAttributeMaxDynamicSharedMemorySize, SM_TOT);

    zero_flags_kernel<<<1, 64>>>();
    init_kernel<<<BATCH, N_H>>>(ic, sew, seb, cew, ceb);
    wconv_kernel<<<256, 256>>>(pcw);
    wconv_hd_kernel<<<16, 256>>>(hdw);
    fused_kernel<<<NREC + NGEMM, 256, SM_TOT>>>(x, iw, l, b, pcb, hdb, out);
}

// round 9
// speedup vs baseline: 1.0021x; 1.0021x over previous
#include <cuda_runtime.h>
#include <cuda_fp16.h>
#include <math.h>
#include <stdint.h>

// Problem constants
#define T_STEPS 1000
#define BATCH   128
#define N_IN    3
#define N_H     256
#define N_PC    256
#define N_HD    12
#define N_IC    268

// Output layout (float32, concatenated in reference tuple order)
#define OFF_HD   0L
#define OFF_PC   (OFF_HD  + (long)T_STEPS * BATCH * N_HD)
#define OFF_BOT  (OFF_PC  + (long)T_STEPS * BATCH * N_PC)
#define OFF_RNN  (OFF_BOT + (long)T_STEPS * BATCH * N_H)
#define OFF_CELL (OFF_RNN + (long)T_STEPS * BATCH * N_H)

// Tile swizzle: rows of 512B; XOR byte-offset bits[4:6] with (row&7).
#define TSWZ(kb, r) ((kb) ^ (((r) & 7) << 4))

#define NREC   128
#define NGEMM  168
#define GQ     (NGEMM / 4)   // 42 blocks per N-quarter

// ---------------------------------------------------------------------------
// Device-global scratch (allocation-free)
// ---------------------------------------------------------------------------
__device__ float g_h0[BATCH * N_H];
__device__ float g_c0[BATCH * N_H];
// Y fp16, pre-swizzled tile images: tile t = [128 batch rows][256 h], 64KB each.
__device__ __half g_yimg[(long)T_STEPS * 128 * 256];
// pc W fp16 images per N-quarter: 64 rows x 256 k = 32KB each.
__device__ __half g_wimg[4][16384];
// hd W fp16 image: 16 rows (12 used) x 256 k = 8KB.
__device__ __half g_hdimg[4096];
// producer->consumer flags: group g done when g_flags[g] == NREC
__device__ int g_flags[64];

// ---------------------------------------------------------------------------
// PTX helpers (base-arch only)
// ---------------------------------------------------------------------------
__device__ __forceinline__ uint32_t smem_u32(const void* p) {
    uint32_t a;
    asm("{ .reg .u64 t; cvta.to.shared.u64 t, %1; cvt.u32.u64 %0, t; }" : "=r"(a) : "l"(p));
    return a;
}
__device__ __forceinline__ void cp_async16(uint32_t dst, const void* src) {
    asm volatile("cp.async.cg.shared.global [%0], [%1], 16;" :: "r"(dst), "l"(src) : "memory");
}
__device__ __forceinline__ void cp_commit() {
    asm volatile("cp.async.commit_group;" ::: "memory");
}
__device__ __forceinline__ void cp_wait1() {
    asm volatile("cp.async.wait_group 1;" ::: "memory");
}
__device__ __forceinline__ void cp_wait0() {
    asm volatile("cp.async.wait_group 0;" ::: "memory");
}
__device__ __forceinline__ void ldsm4(uint32_t& r0, uint32_t& r1, uint32_t& r2, uint32_t& r3,
                                      uint32_t addr) {
    asm volatile("ldmatrix.sync.aligned.m8n8.x4.shared.b16 {%0,%1,%2,%3}, [%4];"
                 : "=r"(r0), "=r"(r1), "=r"(r2), "=r"(r3) : "r"(addr));
}
__device__ __forceinline__ void mma16816(float* c, const uint32_t* a, uint32_t b0, uint32_t b1) {
    asm volatile("mma.sync.aligned.m16n8k16.row.col.f32.f16.f16.f32 "
                 "{%0,%1,%2,%3}, {%4,%5,%6,%7}, {%8,%9}, {%0,%1,%2,%3};"
                 : "+f"(c[0]), "+f"(c[1]), "+f"(c[2]), "+f"(c[3])
                 : "r"(a[0]), "r"(a[1]), "r"(a[2]), "r"(a[3]), "r"(b0), "r"(b1));
}
__device__ __forceinline__ void stcs1(float* p, float v) {
    asm volatile("st.global.cs.f32 [%0], %1;" :: "l"(p), "f"(v) : "memory");
}
__device__ __forceinline__ void stcs2(float* p, float2 v) {
    asm volatile("st.global.cs.v2.f32 [%0], {%1,%2};" :: "l"(p), "f"(v.x), "f"(v.y) : "memory");
}
__device__ __forceinline__ void red_release_add(int* p) {
    asm volatile("red.release.gpu.global.add.s32 [%0], 1;" :: "l"(p) : "memory");
}
__device__ __forceinline__ int ld_acquire(const int* p) {
    int v;
    asm volatile("ld.acquire.gpu.global.s32 %0, [%1];" : "=r"(v) : "l"(p) : "memory");
    return v;
}

// ---------------------------------------------------------------------------
// Kernel 0: zero flags (every call — graph replay safe)
// ---------------------------------------------------------------------------
__global__ void zero_flags_kernel() {
    g_flags[threadIdx.x] = 0;
}

// ---------------------------------------------------------------------------
// Kernel 1: initial conditions
// ---------------------------------------------------------------------------
__global__ void init_kernel(const float* __restrict__ ic,
                            const float* __restrict__ sew, const float* __restrict__ seb,
                            const float* __restrict__ cew, const float* __restrict__ ceb) {
    __shared__ float icr[N_IC];
    int b = blockIdx.x;
    int h = threadIdx.x;
    for (int i = h; i < N_IC; i += N_H) icr[i] = ic[b * N_IC + i];
    __syncthreads();

    float accS = seb[h];
    float accC = ceb[h];
    #pragma unroll 4
    for (int k = 0; k < N_IC; k++) {
        float v = icr[k];
        accS = fmaf(v, sew[k * N_H + h], accS);
        accC = fmaf(v, cew[k * N_H + h], accC);
    }
    g_h0[b * N_H + h] = 1.0f / (1.0f + expf(-accS));
    g_c0[b * N_H + h] = 1.0f / (1.0f + expf(-accC));
}

// ---------------------------------------------------------------------------
// Kernel 2a: pc W -> fp16, pre-swizzled images per N-quarter.
// ---------------------------------------------------------------------------
__global__ void wconv_kernel(const float* __restrict__ W) {
    int k = blockIdx.x;    // 0..255
    int n = threadIdx.x;   // 0..255
    float w = W[k * 256 + n];
    int q = n >> 6, nl = n & 63;
    int byteoff = nl * 512 + TSWZ(k * 2, nl);
    g_wimg[q][byteoff >> 1] = __float2half_rn(w);
}

// Kernel 2b: hd W [256,12] -> padded 16-row fp16 image.
__global__ void wconv_hd_kernel(const float* __restrict__ W) {
    int n = blockIdx.x;    // 0..15
    int k = threadIdx.x;   // 0..255
    float w = (n < N_HD) ? W[k * N_HD + n] : 0.0f;
    int byteoff = n * 512 + TSWZ(k * 2, n);
    g_hdimg[byteoff >> 1] = __float2half_rn(w);
}

// ---------------------------------------------------------------------------
// Fused kernel: blocks 0..127 = recurrence (producer),
//               blocks 128..295 = persistent GEMM (consumer).
// ---------------------------------------------------------------------------
#define SM_A   0
#define SM_B   65536
#define SM_HD  98304
#define SM_TOT 106496

__global__ void __launch_bounds__(256, 2) fused_kernel(
        const float* __restrict__ x,
        const float* __restrict__ iw,
        const float* __restrict__ lvec,
        const float* __restrict__ bvec,
        const float* __restrict__ pcb,
        const float* __restrict__ hdb,
        float* __restrict__ out) {
    extern __shared__ char smem[];
    const int tid = threadIdx.x;

    if (blockIdx.x < NREC) {
        // ============ PRODUCER: recurrence ============
        float* xs = (float*)smem;  // 12 KB of the dynamic region
        const int b = blockIdx.x;
        const int h = tid;

        for (int i = tid; i < T_STEPS * N_IN; i += 256) {
            int t = i / N_IN, c = i - t * N_IN;
            xs[i] = x[((long)t * BATCH + b) * N_IN + c];
        }

        const float w0 = iw[0 * N_H + h];
        const float w1 = iw[1 * N_H + h];
        const float w2 = iw[2 * N_H + h];
        const float lv = lvec[h];
        const float bv = bvec[h];
        float y = g_h0[b * N_H + h];
        float s = g_c0[b * N_H + h];
        __syncthreads();

        float* yp1 = out + OFF_BOT + (long)b * N_H + h;
        float* yp2 = out + OFF_RNN + (long)b * N_H + h;
        float* sp  = out + OFF_CELL + (long)b * N_H + h;
        __half* yi = g_yimg + ((b * 512 + TSWZ(h * 2, b)) >> 1);

        const long strideT = (long)BATCH * N_H;  // 32768

        for (int t = 0; t < T_STEPS; t++) {
            const float x0 = xs[t * 3 + 0];
            const float x1 = xs[t * 3 + 1];
            const float x2 = xs[t * 3 + 2];
            float xw  = fmaf(x2, w2, fmaf(x1, w1, x0 * w0));
            float pre = xw + y + lv * s * (1.0f - y);
            s = fmaxf(pre, 0.0f);
            y = (s + bv > 0.0f) ? 1.0f : 0.0f;

            long o = (long)t * strideT;
            stcs1(yp1 + o, y);
            stcs1(yp2 + o, y);
            stcs1(sp + o, s);
            yi[(long)t * 32768] = __float2half_rn(y);   // plain store: keep L2-hot

            if (((t & 15) == 15) || (t == T_STEPS - 1)) {
                __syncthreads();                         // all lanes' stores done
                if (tid == 0) red_release_add(&g_flags[t >> 4]);
            }
        }
    } else {
        // ============ CONSUMER: persistent GEMM ============
        uint32_t sb = smem_u32(smem);
        const int wid = tid >> 5, lane = tid & 31;
        const int gid = (int)blockIdx.x - NREC;   // 0..167
        const int q   = gid & 3;                  // fixed N-quarter
        const int t0  = gid >> 2;                 // 0..41
        const int warp_m = wid & 3, warp_n = wid >> 2;  // 4m x 2n
        const bool hdq = (q == 0) && (warp_n == 0);

        // Load B quarter (32KB) once; hd image (8KB) for q==0 blocks.
        {
            const char* gW = (const char*)(g_wimg[q]);
            #pragma unroll
            for (int i = 0; i < 8; i++)
                cp_async16(sb + SM_B + (tid + i * 256) * 16, gW + (tid + i * 256) * 16);
            if (q == 0) {
                const char* gH = (const char*)g_hdimg;
                #pragma unroll
                for (int i = 0; i < 2; i++)
                    cp_async16(sb + SM_HD + (tid + i * 256) * 16, gH + (tid + i * 256) * 16);
            }
            cp_commit();
            cp_wait0();
        }
        __syncthreads();

        const int g  = lane >> 2;
        const int c2 = (lane & 3) * 2;
        const int colBase = q * 64 + warp_n * 32;

        float2 bias2[4];
        #pragma unroll
        for (int ni = 0; ni < 4; ni++) {
            bias2[ni].x = __ldg(pcb + colBase + ni * 8 + c2);
            bias2[ni].y = __ldg(pcb + colBase + ni * 8 + c2 + 1);
        }
        float hb0x = 0.f, hb0y = 0.f, hb1x = 0.f, hb1y = 0.f;
        if (hdq) {
            hb0x = __ldg(hdb + c2);
            hb0y = __ldg(hdb + c2 + 1);
            if (c2 < 4) { hb1x = __ldg(hdb + 8 + c2); hb1y = __ldg(hdb + 8 + c2 + 1); }
        }

        const int arow0 = warp_m * 32 + (lane & 15);
        const int brow0 = warp_n * 32 + (lane & 15);
        const int hrow0 = (lane & 15);
        const int ksub  = (lane >> 4) * 16;
        const int r_ld  = tid >> 1;        // 0..127
        const int p_ld  = (tid & 1) * 128; // byte offset within a 256B half-row

        for (int t = t0; t < T_STEPS; t += GQ) {
            // Wait for tile t (group t>>4 complete).
            if (tid == 0) {
                const int* fp = &g_flags[t >> 4];
                while (ld_acquire(fp) < NREC) __nanosleep(64);
            }
            __syncthreads();   // releases block; also guards A-buffer reuse

            // Load A tile in two k-halves (columns [0,128) then [128,256)).
            const char* gA = (const char*)(g_yimg + (long)t * 32768);
            #pragma unroll
            for (int j = 0; j < 8; j++)
                cp_async16(sb + SM_A + r_ld * 512 + p_ld + j * 16,
                           gA + r_ld * 512 + p_ld + j * 16);
            cp_commit();
            #pragma unroll
            for (int j = 0; j < 8; j++)
                cp_async16(sb + SM_A + r_ld * 512 + 256 + p_ld + j * 16,
                           gA + r_ld * 512 + 256 + p_ld + j * 16);
            cp_commit();

            float acc[2][4][4];
            #pragma unroll
            for (int i = 0; i < 2; i++)
                #pragma unroll
                for (int j = 0; j < 4; j++)
                    #pragma unroll
                    for (int p = 0; p < 4; p++) acc[i][j][p] = 0.0f;
            float acch[2][2][4];
            #pragma unroll
            for (int i = 0; i < 2; i++)
                #pragma unroll
                for (int j = 0; j < 2; j++)
                    #pragma unroll
                    for (int p = 0; p < 4; p++) acch[i][j][p] = 0.0f;

            #pragma unroll
            for (int kh = 0; kh < 2; kh++) {
                if (kh == 0) cp_wait1(); else cp_wait0();
                __syncthreads();
                #pragma unroll
                for (int kk = 0; kk < 8; kk++) {
                    const int kb = (kh * 8 + kk) * 32 + ksub;
                    uint32_t a[2][4], bfr[2][4];
                    #pragma unroll
                    for (int mi = 0; mi < 2; mi++) {
                        int r = arow0 + mi * 16;
                        ldsm4(a[mi][0], a[mi][1], a[mi][2], a[mi][3],
                              sb + SM_A + r * 512 + TSWZ(kb, r));
                    }
                    #pragma unroll
                    for (int ni = 0; ni < 2; ni++) {
                        int r = brow0 + ni * 16;
                        ldsm4(bfr[ni][0], bfr[ni][1], bfr[ni][2], bfr[ni][3],
                              sb + SM_B + r * 512 + TSWZ(kb, r));
                    }
                    #pragma unroll
                    for (int mi = 0; mi < 2; mi++)
                        #pragma unroll
                        for (int ni = 0; ni < 2; ni++) {
                            mma16816(acc[mi][ni * 2],     a[mi], bfr[ni][0], bfr[ni][2]);
                            mma16816(acc[mi][ni * 2 + 1], a[mi], bfr[ni][1], bfr[ni][3]);
                        }
                    if (hdq) {
                        uint32_t hb[4];
                        ldsm4(hb[0], hb[1], hb[2], hb[3],
                              sb + SM_HD + hrow0 * 512 + TSWZ(kb, hrow0));
                        #pragma unroll
                        for (int mi = 0; mi < 2; mi++) {
                            mma16816(acch[mi][0], a[mi], hb[0], hb[2]);
                            mma16816(acch[mi][1], a[mi], hb[1], hb[3]);
                        }
                    }
                }
            }

            // Epilogue: pc
            const long rowBase = (long)t * 128 + warp_m * 32;
            float* outpc = out + OFF_PC;
            #pragma unroll
            for (int mi = 0; mi < 2; mi++) {
                float* r0 = outpc + (rowBase + mi * 16 + g) * N_PC + colBase + c2;
                float* r1 = r0 + 8 * N_PC;
                #pragma unroll
                for (int ni = 0; ni < 4; ni++) {
                    stcs2(r0 + ni * 8, make_float2(acc[mi][ni][0] + bias2[ni].x,
                                                   acc[mi][ni][1] + bias2[ni].y));
                    stcs2(r1 + ni * 8, make_float2(acc[mi][ni][2] + bias2[ni].x,
                                                   acc[mi][ni][3] + bias2[ni].y));
                }
            }
            // Epilogue: hd (cols 0..11 of the padded 16)
            if (hdq) {
                float* outhd = out + OFF_HD;
                #pragma unroll
                for (int mi = 0; mi < 2; mi++) {
                    long r = rowBase + mi * 16 + g;
                    float* o0 = outhd + r * N_HD;
                    float* o1 = o0 + 8L * N_HD;
                    stcs2(o0 + c2, make_float2(acch[mi][0][0] + hb0x, acch[mi][0][1] + hb0y));
                    stcs2(o1 + c2, make_float2(acch[mi][0][2] + hb0x, acch[mi][0][3] + hb0y));
                    if (c2 < 4) {
                        stcs2(o0 + 8 + c2, make_float2(acch[mi][1][0] + hb1x, acch[mi][1][1] + hb1y));
                        stcs2(o1 + 8 + c2, make_float2(acch[mi][1][2] + hb1x, acch[mi][1][3] + hb1y));
                    }
                }
            }
        }
    }
}

// ---------------------------------------------------------------------------
extern "C" void kernel_launch(void* const* d_in, const int* in_sizes, int n_in,
                              void* d_out, int out_size) {
    const float* x    = (const float*)d_in[0];
    const float* ic   = (const float*)d_in[1];
    const float* iw   = (const float*)d_in[2];
    const float* l    = (const float*)d_in[3];
    const float* b    = (const float*)d_in[4];
    const float* sew  = (const float*)d_in[5];
    const float* seb  = (const float*)d_in[6];
    const float* cew  = (const float*)d_in[7];
    const float* ceb  = (const float*)d_in[8];
    const float* pcw  = (const float*)d_in[9];
    const float* pcb  = (const float*)d_in[10];
    const float* hdw  = (const float*)d_in[11];
    const float* hdb  = (const float*)d_in[12];
    float* out = (float*)d_out;

    cudaFuncSetAttribute(fused_kernel, cudaFuncAttributeMaxDynamicSharedMemorySize, SM_TOT);

    zero_flags_kernel<<<1, 64>>>();
    init_kernel<<<BATCH, N_H>>>(ic, sew, seb, cew, ceb);
    wconv_kernel<<<256, 256>>>(pcw);
    wconv_hd_kernel<<<16, 256>>>(hdw);
    fused_kernel<<<NREC + NGEMM, 256, SM_TOT>>>(x, iw, l, b, pcb, hdb, out);
}

// round 10
// speedup vs baseline: 1.3959x; 1.3930x over previous
#include <cuda_runtime.h>
#include <cuda_fp16.h>
#include <math.h>
#include <stdint.h>

// Problem constants
#define T_STEPS 1000
#define BATCH   128
#define N_IN    3
#define N_H     256
#define N_PC    256
#define N_HD    12
#define N_IC    268

// Output layout (float32, concatenated in reference tuple order)
#define OFF_HD   0L
#define OFF_PC   (OFF_HD  + (long)T_STEPS * BATCH * N_HD)
#define OFF_BOT  (OFF_PC  + (long)T_STEPS * BATCH * N_PC)
#define OFF_RNN  (OFF_BOT + (long)T_STEPS * BATCH * N_H)
#define OFF_CELL (OFF_RNN + (long)T_STEPS * BATCH * N_H)

// Tile swizzle: rows of 512B; XOR byte-offset bits[4:6] with (row&7).
#define TSWZ(kb, r) ((kb) ^ (((r) & 7) << 4))

// ---------------------------------------------------------------------------
// Device-global scratch (allocation-free)
// ---------------------------------------------------------------------------
__device__ float g_h0[BATCH * N_H];
__device__ float g_c0[BATCH * N_H];
// Y fp16, pre-swizzled tile images: tile t = [128 batch rows][256 h], 64KB each.
__device__ __half g_yimg[(long)T_STEPS * 128 * 256];
// pc W fp16 images per N-half: 128 rows x 256 k = 64KB each.
__device__ __half g_wimg[2][32768];
// hd W fp16 image: 16 rows (12 used) x 256 k = 8KB.
__device__ __half g_hdimg[4096];

// ---------------------------------------------------------------------------
// PTX helpers (base-arch only)
// ---------------------------------------------------------------------------
__device__ __forceinline__ uint32_t smem_u32(const void* p) {
    uint32_t a;
    asm("{ .reg .u64 t; cvta.to.shared.u64 t, %1; cvt.u32.u64 %0, t; }" : "=r"(a) : "l"(p));
    return a;
}
__device__ __forceinline__ void cp_async16(uint32_t dst, const void* src) {
    asm volatile("cp.async.cg.shared.global [%0], [%1], 16;" :: "r"(dst), "l"(src) : "memory");
}
__device__ __forceinline__ void cp_commit() {
    asm volatile("cp.async.commit_group;" ::: "memory");
}
__device__ __forceinline__ void cp_wait1() {
    asm volatile("cp.async.wait_group 1;" ::: "memory");
}
__device__ __forceinline__ void cp_wait0() {
    asm volatile("cp.async.wait_group 0;" ::: "memory");
}
__device__ __forceinline__ void ldsm4(uint32_t& r0, uint32_t& r1, uint32_t& r2, uint32_t& r3,
                                      uint32_t addr) {
    asm volatile("ldmatrix.sync.aligned.m8n8.x4.shared.b16 {%0,%1,%2,%3}, [%4];"
                 : "=r"(r0), "=r"(r1), "=r"(r2), "=r"(r3) : "r"(addr));
}
__device__ __forceinline__ void mma16816(float* c, const uint32_t* a, uint32_t b0, uint32_t b1) {
    asm volatile("mma.sync.aligned.m16n8k16.row.col.f32.f16.f16.f32 "
                 "{%0,%1,%2,%3}, {%4,%5,%6,%7}, {%8,%9}, {%0,%1,%2,%3};"
                 : "+f"(c[0]), "+f"(c[1]), "+f"(c[2]), "+f"(c[3])
                 : "r"(a[0]), "r"(a[1]), "r"(a[2]), "r"(a[3]), "r"(b0), "r"(b1));
}
__device__ __forceinline__ void stcs1(float* p, float v) {
    asm volatile("st.global.cs.f32 [%0], %1;" :: "l"(p), "f"(v) : "memory");
}
__device__ __forceinline__ void stcs2(float* p, float2 v) {
    asm volatile("st.global.cs.v2.f32 [%0], {%1,%2};" :: "l"(p), "f"(v.x), "f"(v.y) : "memory");
}

// ---------------------------------------------------------------------------
// Kernel 1: fused prologue.
// blocks 0..127:   init (h0/c0)
// blocks 128..383: pc W conversion (k = bid-128)
// blocks 384..399: hd W conversion (n = bid-384)
// ---------------------------------------------------------------------------
__global__ void __launch_bounds__(256) prep_kernel(
        const float* __restrict__ ic,
        const float* __restrict__ sew, const float* __restrict__ seb,
        const float* __restrict__ cew, const float* __restrict__ ceb,
        const float* __restrict__ pcw, const float* __restrict__ hdw) {
    const int bid = blockIdx.x;
    const int tid = threadIdx.x;

    if (bid < 128) {
        __shared__ float icr[N_IC];
        int b = bid;
        int h = tid;
        for (int i = h; i < N_IC; i += N_H) icr[i] = ic[b * N_IC + i];
        __syncthreads();

        float accS = seb[h];
        float accC = ceb[h];
        #pragma unroll 4
        for (int k = 0; k < N_IC; k++) {
            float v = icr[k];
            accS = fmaf(v, sew[k * N_H + h], accS);
            accC = fmaf(v, cew[k * N_H + h], accC);
        }
        g_h0[b * N_H + h] = 1.0f / (1.0f + expf(-accS));
        g_c0[b * N_H + h] = 1.0f / (1.0f + expf(-accC));
    } else if (bid < 384) {
        int k = bid - 128;   // 0..255
        int n = tid;         // 0..255
        float w = pcw[k * 256 + n];
        int nh = n >> 7, nl = n & 127;
        int byteoff = nl * 512 + TSWZ(k * 2, nl);
        g_wimg[nh][byteoff >> 1] = __float2half_rn(w);
    } else {
        int n = bid - 384;   // 0..15
        int k = tid;         // 0..255
        float w = (n < N_HD) ? hdw[k * N_HD + n] : 0.0f;
        int byteoff = n * 512 + TSWZ(k * 2, n);
        g_hdimg[byteoff >> 1] = __float2half_rn(w);
    }
}

// ---------------------------------------------------------------------------
// Kernel 2: recurrence. grid=(128,2) (batch, h-half), 128 threads (one per h).
// Stores: y fp32 -> BOT,RNN (streaming); s fp32 -> CELL; y fp16 -> image.
// ---------------------------------------------------------------------------
__global__ void __launch_bounds__(128) rec_kernel(const float* __restrict__ x,
                                                  const float* __restrict__ iw,
                                                  const float* __restrict__ lvec,
                                                  const float* __restrict__ bvec,
                                                  float* __restrict__ out) {
    __shared__ float xs[T_STEPS * N_IN];  // 12 KB
    const int b = blockIdx.x;
    const int h = blockIdx.y * 128 + threadIdx.x;

    for (int i = threadIdx.x; i < T_STEPS * N_IN; i += 128) {
        int t = i / N_IN, c = i - t * N_IN;
        xs[i] = x[((long)t * BATCH + b) * N_IN + c];
    }

    const float w0 = iw[0 * N_H + h];
    const float w1 = iw[1 * N_H + h];
    const float w2 = iw[2 * N_H + h];
    const float lv = lvec[h];
    const float bv = bvec[h];
    float y = g_h0[b * N_H + h];
    float s = g_c0[b * N_H + h];
    __syncthreads();

    float* yp1 = out + OFF_BOT + (long)b * N_H + h;
    float* yp2 = out + OFF_RNN + (long)b * N_H + h;
    float* sp  = out + OFF_CELL + (long)b * N_H + h;
    __half* yi = g_yimg + ((b * 512 + TSWZ(h * 2, b)) >> 1);

    const long strideT = (long)BATCH * N_H;  // 32768

    for (int t = 0; t < T_STEPS; t++) {
        const float x0 = xs[t * 3 + 0];
        const float x1 = xs[t * 3 + 1];
        const float x2 = xs[t * 3 + 2];
        float xw  = fmaf(x2, w2, fmaf(x1, w1, x0 * w0));
        float pre = xw + y + lv * s * (1.0f - y);
        s = fmaxf(pre, 0.0f);
        y = (s + bv > 0.0f) ? 1.0f : 0.0f;

        long o = (long)t * strideT;
        stcs1(yp1 + o, y);
        stcs1(yp2 + o, y);
        stcs1(sp + o, s);
        yi[(long)t * 32768] = __float2half_rn(y);   // plain store: stays L2-warm
    }
}

// ---------------------------------------------------------------------------
// Kernel 3: persistent pc GEMM + fused hd. grid=148, 512 threads, 200KB SMEM.
// Block i<74: N-half 0 (t = i, i+74, ...); i>=74: N-half 1 (t = i-74, ...).
// A tiles double-buffered via cp.async; B (64KB) + hd (8KB) loaded once.
// 16 warps: warp_m = wid&3 (32 rows), warp_n = wid>>2 (32 cols).
// ---------------------------------------------------------------------------
#define SM_A0  0
#define SM_A1  65536
#define SM_B   131072
#define SM_HD  196608
#define SM_TOT 204800
#define TSTRIDE 74

__global__ void __launch_bounds__(512, 1) pc_gemm(const float* __restrict__ pcb,
                                                  const float* __restrict__ hdb,
                                                  float* __restrict__ out) {
    extern __shared__ char smem[];
    uint32_t sb = smem_u32(smem);
    const int tid = threadIdx.x, wid = tid >> 5, lane = tid & 31;
    const int bi = (int)blockIdx.x;
    const int nh = (bi >= TSTRIDE) ? 1 : 0;
    const int tstart = nh ? bi - TSTRIDE : bi;
    const int warp_m = wid & 3, warp_n = wid >> 2;
    const bool hdq = (nh == 0) && (warp_n == 0);

    // Load B half (64KB) once; hd image (8KB) for nh==0 blocks. group #1
    {
        const char* gW = (const char*)(g_wimg[nh]);
        #pragma unroll
        for (int i = 0; i < 8; i++)
            cp_async16(sb + SM_B + (tid + i * 512) * 16, gW + (tid + i * 512) * 16);
        if (nh == 0) {
            const char* gH = (const char*)g_hdimg;
            cp_async16(sb + SM_HD + tid * 16, gH + tid * 16);
        }
        cp_commit();
    }
    // Prefetch first A tile into buf0. group #2
    {
        const char* gA = (const char*)(g_yimg + (long)tstart * 32768);
        #pragma unroll
        for (int i = 0; i < 8; i++)
            cp_async16(sb + SM_A0 + (tid + i * 512) * 16, gA + (tid + i * 512) * 16);
        cp_commit();
    }

    const int g  = lane >> 2;
    const int c2 = (lane & 3) * 2;
    const int colBase = nh * 128 + warp_n * 32;

    float2 bias2[4];
    #pragma unroll
    for (int ni = 0; ni < 4; ni++) {
        bias2[ni].x = __ldg(pcb + colBase + ni * 8 + c2);
        bias2[ni].y = __ldg(pcb + colBase + ni * 8 + c2 + 1);
    }
    float hb0x = 0.f, hb0y = 0.f, hb1x = 0.f, hb1y = 0.f;
    if (hdq) {
        hb0x = __ldg(hdb + c2);
        hb0y = __ldg(hdb + c2 + 1);
        if (c2 < 4) { hb1x = __ldg(hdb + 8 + c2); hb1y = __ldg(hdb + 8 + c2 + 1); }
    }

    const int arow0 = warp_m * 32 + (lane & 15);
    const int brow0 = warp_n * 32 + (lane & 15);
    const int hrow0 = (lane & 15);
    const int ksub  = (lane >> 4) * 16;

    int buf = 0;
    for (int t = tstart; t < T_STEPS; t += TSTRIDE) {
        const int tn = t + TSTRIDE;
        if (tn < T_STEPS) {
            // Prefetch next A tile into the other buffer.
            const uint32_t dst = sb + (buf ? SM_A0 : SM_A1);
            const char* gA = (const char*)(g_yimg + (long)tn * 32768);
            #pragma unroll
            for (int i = 0; i < 8; i++)
                cp_async16(dst + (tid + i * 512) * 16, gA + (tid + i * 512) * 16);
            cp_commit();
            cp_wait1();   // current tile (and B) resident; next still in flight
        } else {
            cp_wait0();
        }
        __syncthreads();

        const uint32_t abase = sb + (buf ? SM_A1 : SM_A0);

        float acc[2][4][4];
        #pragma unroll
        for (int i = 0; i < 2; i++)
            #pragma unroll
            for (int j = 0; j < 4; j++)
                #pragma unroll
                for (int p = 0; p < 4; p++) acc[i][j][p] = 0.0f;
        float acch[2][2][4];
        #pragma unroll
        for (int i = 0; i < 2; i++)
            #pragma unroll
            for (int j = 0; j < 2; j++)
                #pragma unroll
                for (int p = 0; p < 4; p++) acch[i][j][p] = 0.0f;

        #pragma unroll
        for (int k16 = 0; k16 < 16; k16++) {
            const int kb = k16 * 32 + ksub;
            uint32_t a[2][4], bfr[2][4];
            #pragma unroll
            for (int mi = 0; mi < 2; mi++) {
                int r = arow0 + mi * 16;
                ldsm4(a[mi][0], a[mi][1], a[mi][2], a[mi][3],
                      abase + r * 512 + TSWZ(kb, r));
            }
            #pragma unroll
            for (int ni = 0; ni < 2; ni++) {
                int r = brow0 + ni * 16;
                ldsm4(bfr[ni][0], bfr[ni][1], bfr[ni][2], bfr[ni][3],
                      sb + SM_B + r * 512 + TSWZ(kb, r));
            }
            #pragma unroll
            for (int mi = 0; mi < 2; mi++)
                #pragma unroll
                for (int ni = 0; ni < 2; ni++) {
                    mma16816(acc[mi][ni * 2],     a[mi], bfr[ni][0], bfr[ni][2]);
                    mma16816(acc[mi][ni * 2 + 1], a[mi], bfr[ni][1], bfr[ni][3]);
                }
            if (hdq) {
                uint32_t hb[4];
                ldsm4(hb[0], hb[1], hb[2], hb[3],
                      sb + SM_HD + hrow0 * 512 + TSWZ(kb, hrow0));
                #pragma unroll
                for (int mi = 0; mi < 2; mi++) {
                    mma16816(acch[mi][0], a[mi], hb[0], hb[2]);
                    mma16816(acch[mi][1], a[mi], hb[1], hb[3]);
                }
            }
        }

        // Epilogue: pc
        const long rowBase = (long)t * 128 + warp_m * 32;
        float* outpc = out + OFF_PC;
        #pragma unroll
        for (int mi = 0; mi < 2; mi++) {
            float* r0 = outpc + (rowBase + mi * 16 + g) * N_PC + colBase + c2;
            float* r1 = r0 + 8 * N_PC;
            #pragma unroll
            for (int ni = 0; ni < 4; ni++) {
                stcs2(r0 + ni * 8, make_float2(acc[mi][ni][0] + bias2[ni].x,
                                               acc[mi][ni][1] + bias2[ni].y));
                stcs2(r1 + ni * 8, make_float2(acc[mi][ni][2] + bias2[ni].x,
                                               acc[mi][ni][3] + bias2[ni].y));
            }
        }
        // Epilogue: hd (cols 0..11 of the padded 16)
        if (hdq) {
            float* outhd = out + OFF_HD;
            #pragma unroll
            for (int mi = 0; mi < 2; mi++) {
                long r = rowBase + mi * 16 + g;
                float* o0 = outhd + r * N_HD;
                float* o1 = o0 + 8L * N_HD;
                stcs2(o0 + c2, make_float2(acch[mi][0][0] + hb0x, acch[mi][0][1] + hb0y));
                stcs2(o1 + c2, make_float2(acch[mi][0][2] + hb0x, acch[mi][0][3] + hb0y));
                if (c2 < 4) {
                    stcs2(o0 + 8 + c2, make_float2(acch[mi][1][0] + hb1x, acch[mi][1][1] + hb1y));
                    stcs2(o1 + 8 + c2, make_float2(acch[mi][1][2] + hb1x, acch[mi][1][3] + hb1y));
                }
            }
        }

        __syncthreads();   // all warps done reading this A buffer before reuse
        buf ^= 1;
    }
}

// ---------------------------------------------------------------------------
extern "C" void kernel_launch(void* const* d_in, const int* in_sizes, int n_in,
                              void* d_out, int out_size) {
    const float* x    = (const float*)d_in[0];
    const float* ic   = (const float*)d_in[1];
    const float* iw   = (const float*)d_in[2];
    const float* l    = (const float*)d_in[3];
    const float* b    = (const float*)d_in[4];
    const float* sew  = (const float*)d_in[5];
    const float* seb  = (const float*)d_in[6];
    const float* cew  = (const float*)d_in[7];
    const float* ceb  = (const float*)d_in[8];
    const float* pcw  = (const float*)d_in[9];
    const float* pcb  = (const float*)d_in[10];
    const float* hdw  = (const float*)d_in[11];
    const float* hdb  = (const float*)d_in[12];
    float* out = (float*)d_out;

    cudaFuncSetAttribute(pc_gemm, cudaFuncAttributeMaxDynamicSharedMemorySize, SM_TOT);

    prep_kernel<<<400, 256>>>(ic, sew, seb, cew, ceb, pcw, hdw);
    rec_kernel<<<dim3(BATCH, 2), 128>>>(x, iw, l, b, out);
    pc_gemm<<<148, 512, SM_TOT>>>(pcb, hdb, out);
}